// round 13
// baseline (speedup 1.0000x reference)
#include <cuda_runtime.h>
#include <cuda_bf16.h>
#include <cstdint>

#define N_MOLS   2048
#define N_NODES  51200
#define N_EDGES  102400
#define MAX_NB   6
#define HIDDEN   300
#define NODE_FDIM 133
#define EDGE_FDIM 147
#define DEPTH    6
#define H4       75
#define MPAD     320
#define FEPAD    160
#define CATPAD   448

// ---------------- scratch -----------------------------------------------------
__device__ float g_inp [N_EDGES * HIDDEN];
__device__ __align__(16) __nv_bfloat16 g_msgh[N_EDGES * MPAD];
__device__ __align__(16) __nv_bfloat16 g_msgl[N_EDGES * MPAD];
__device__ float g_G   [N_EDGES * HIDDEN];
__device__ float g_S   [N_NODES * HIDDEN];
__device__ __align__(16) __nv_bfloat16 g_feh [N_EDGES * FEPAD];
__device__ __align__(16) __nv_bfloat16 g_fel [N_EDGES * FEPAD];
__device__ __align__(16) __nv_bfloat16 g_cath[N_NODES * CATPAD];
__device__ __align__(16) __nv_bfloat16 g_catl[N_NODES * CATPAD];
__device__ __align__(16) __nv_bfloat16 g_Wth [MPAD * MPAD];
__device__ __align__(16) __nv_bfloat16 g_Wtl [MPAD * MPAD];
__device__ __align__(16) __nv_bfloat16 g_Wih [MPAD * FEPAD];
__device__ __align__(16) __nv_bfloat16 g_Wil [MPAD * FEPAD];
__device__ __align__(16) __nv_bfloat16 g_Woh [MPAD * CATPAD];
__device__ __align__(16) __nv_bfloat16 g_Wol [MPAD * CATPAD];
__device__ int   g_cnt [N_MOLS];

// ---------------- helpers -----------------------------------------------------
__device__ __forceinline__ void bsplit(float x, __nv_bfloat16& h, __nv_bfloat16& l) {
    h = __float2bfloat16(x);
    l = __float2bfloat16(x - __bfloat162float(h));
}

__device__ __forceinline__ void mma_bf16(float* d, const uint32_t* a, const uint32_t* b) {
    asm volatile(
        "mma.sync.aligned.m16n8k16.row.col.f32.bf16.bf16.f32 "
        "{%0,%1,%2,%3}, {%4,%5,%6,%7}, {%8,%9}, {%0,%1,%2,%3};\n"
        : "+f"(d[0]), "+f"(d[1]), "+f"(d[2]), "+f"(d[3])
        : "r"(a[0]), "r"(a[1]), "r"(a[2]), "r"(a[3]), "r"(b[0]), "r"(b[1]));
}

__device__ __forceinline__ void cp16(__nv_bfloat16* dst, const __nv_bfloat16* src) {
    const uint32_t sa = (uint32_t)__cvta_generic_to_shared(dst);
    asm volatile("cp.async.cg.shared.global [%0], [%1], 16;\n" :: "r"(sa), "l"(src));
}
__device__ __forceinline__ void cp_commit() {
    asm volatile("cp.async.commit_group;\n");
}
template<int N>
__device__ __forceinline__ void cp_wait() {
    asm volatile("cp.async.wait_group %0;\n" :: "n"(N));
}

#define BM 128
#define BN 64
#define ASTR 40
#define A_CH (BM * ASTR)     // 5120 elems per A chunk
#define B_SZ (BN * ASTR)     // 2560 elems per B stage

// =============== A-resident GEMM (modes 0 and 1): n-loop in kernel ============
// A (BM x KSTR, hi+lo) streamed into smem ONCE during ns=0, reused for ns=1..4.
// MODE 0: g_G = msg @ W_h          (KSTR=320, KCH=10)  smem 225280 B
// MODE 1: inp/msg = f_edges @ W_i  (KSTR=160, KCH=5)   smem 122880 B
#define NSUB (MPAD / BN)     // 5 n-subtiles
template<int MODE, int KCH, int KSTR>
__launch_bounds__(256)
__global__ void mma_gemm_ares_k()
{
    extern __shared__ __nv_bfloat16 sm[];
    __nv_bfloat16* Ahr = sm;                         // [KCH][BM][ASTR]
    __nv_bfloat16* Alr = sm + KCH * A_CH;            // [KCH][BM][ASTR]
    __nv_bfloat16* Bh2 = sm + 2 * KCH * A_CH;        // [2][BN][ASTR]
    __nv_bfloat16* Bl2 = Bh2 + 2 * B_SZ;             // [2][BN][ASTR]

    const __nv_bfloat16* __restrict__ Asrc_h = (MODE == 0) ? g_msgh : g_feh;
    const __nv_bfloat16* __restrict__ Asrc_l = (MODE == 0) ? g_msgl : g_fel;
    const __nv_bfloat16* __restrict__ Bsrc_h = (MODE == 0) ? g_Wth : g_Wih;
    const __nv_bfloat16* __restrict__ Bsrc_l = (MODE == 0) ? g_Wtl : g_Wil;

    const int tid  = threadIdx.x;
    const int lane = tid & 31;
    const int wid  = tid >> 5;
    const int wm   = (wid >> 1) * 32;
    const int wn   = (wid & 1) * 32;
    const int g    = lane >> 2;
    const int tg   = lane & 3;
    const int m0   = blockIdx.x * BM;

    const int arow = tid >> 2;        // 0..63
    const int acol = (tid & 3) * 8;

    auto issueA = [&](int c) {
        const int k0 = c * 32;
        #pragma unroll
        for (int i = 0; i < 2; i++) {
            const int r = arow + i * 64;
            const size_t go = (size_t)(m0 + r) * KSTR + k0 + acol;
            cp16(Ahr + c * A_CH + r * ASTR + acol, Asrc_h + go);
            cp16(Alr + c * A_CH + r * ASTR + acol, Asrc_l + go);
        }
    };
    auto issueB = [&](int ns, int c, int st) {
        const size_t go = (size_t)(ns * BN + arow) * KSTR + c * 32 + acol;
        cp16(Bh2 + st * B_SZ + arow * ASTR + acol, Bsrc_h + go);
        cp16(Bl2 + st * B_SZ + arow * ASTR + acol, Bsrc_l + go);
    };

    float d[2][4][4];

    #pragma unroll 1
    for (int ns = 0; ns < NSUB; ns++) {
        #pragma unroll
        for (int mt = 0; mt < 2; mt++)
            #pragma unroll
            for (int nt = 0; nt < 4; nt++)
                #pragma unroll
                for (int r = 0; r < 4; r++) d[mt][nt][r] = 0.f;

        // prologue for this subtile
        if (ns == 0) { issueA(0); }
        issueB(ns, 0, 0);
        cp_commit();

        #pragma unroll 1
        for (int c = 0; c < KCH; c++) {
            const int st = c & 1;
            if (c + 1 < KCH) {
                if (ns == 0) issueA(c + 1);
                issueB(ns, c + 1, (c + 1) & 1);
                cp_commit();
                cp_wait<1>();
            } else {
                cp_wait<0>();
            }
            __syncthreads();

            const __nv_bfloat16* sAh = Ahr + c * A_CH;
            const __nv_bfloat16* sAl = Alr + c * A_CH;
            const __nv_bfloat16* sBh = Bh2 + st * B_SZ;
            const __nv_bfloat16* sBl = Bl2 + st * B_SZ;

            #pragma unroll
            for (int kk = 0; kk < 32; kk += 16) {
                uint32_t ah[2][4], al[2][4], bh[4][2], bl[4][2];
                #pragma unroll
                for (int mt = 0; mt < 2; mt++) {
                    const int row = wm + mt * 16;
                    ah[mt][0] = *(const uint32_t*)&sAh[(row + g    ) * ASTR + kk + 2*tg    ];
                    ah[mt][1] = *(const uint32_t*)&sAh[(row + g + 8) * ASTR + kk + 2*tg    ];
                    ah[mt][2] = *(const uint32_t*)&sAh[(row + g    ) * ASTR + kk + 2*tg + 8];
                    ah[mt][3] = *(const uint32_t*)&sAh[(row + g + 8) * ASTR + kk + 2*tg + 8];
                    al[mt][0] = *(const uint32_t*)&sAl[(row + g    ) * ASTR + kk + 2*tg    ];
                    al[mt][1] = *(const uint32_t*)&sAl[(row + g + 8) * ASTR + kk + 2*tg    ];
                    al[mt][2] = *(const uint32_t*)&sAl[(row + g    ) * ASTR + kk + 2*tg + 8];
                    al[mt][3] = *(const uint32_t*)&sAl[(row + g + 8) * ASTR + kk + 2*tg + 8];
                }
                #pragma unroll
                for (int nt = 0; nt < 4; nt++) {
                    const int col = wn + nt * 8 + g;
                    bh[nt][0] = *(const uint32_t*)&sBh[col * ASTR + kk + 2*tg    ];
                    bh[nt][1] = *(const uint32_t*)&sBh[col * ASTR + kk + 2*tg + 8];
                    bl[nt][0] = *(const uint32_t*)&sBl[col * ASTR + kk + 2*tg    ];
                    bl[nt][1] = *(const uint32_t*)&sBl[col * ASTR + kk + 2*tg + 8];
                }
                #pragma unroll
                for (int mt = 0; mt < 2; mt++)
                    #pragma unroll
                    for (int nt = 0; nt < 4; nt++) {
                        mma_bf16(d[mt][nt], ah[mt], bh[nt]);
                        mma_bf16(d[mt][nt], ah[mt], bl[nt]);
                        mma_bf16(d[mt][nt], al[mt], bh[nt]);
                    }
            }
            __syncthreads();
        }

        // ---- epilogue for this n-subtile ----
        const int n0 = ns * BN;
        #pragma unroll
        for (int mt = 0; mt < 2; mt++) {
            const int gm = m0 + wm + mt * 16 + g;
            #pragma unroll
            for (int nt = 0; nt < 4; nt++) {
                const int gn = n0 + wn + nt * 8 + 2 * tg;
                if (gn < HIDDEN) {
                    if (MODE == 0) {
                        *(float2*)&g_G[(size_t)gm * HIDDEN + gn]       = make_float2(d[mt][nt][0], d[mt][nt][1]);
                        *(float2*)&g_G[(size_t)(gm + 8) * HIDDEN + gn] = make_float2(d[mt][nt][2], d[mt][nt][3]);
                    } else {
                        *(float2*)&g_inp[(size_t)gm * HIDDEN + gn]       = make_float2(d[mt][nt][0], d[mt][nt][1]);
                        *(float2*)&g_inp[(size_t)(gm + 8) * HIDDEN + gn] = make_float2(d[mt][nt][2], d[mt][nt][3]);
                        __nv_bfloat16 h0, l0, h1, l1;
                        bsplit(fmaxf(d[mt][nt][0], 0.f), h0, l0);
                        bsplit(fmaxf(d[mt][nt][1], 0.f), h1, l1);
                        g_msgh[(size_t)gm * MPAD + gn]     = h0;
                        g_msgh[(size_t)gm * MPAD + gn + 1] = h1;
                        g_msgl[(size_t)gm * MPAD + gn]     = l0;
                        g_msgl[(size_t)gm * MPAD + gn + 1] = l1;
                        bsplit(fmaxf(d[mt][nt][2], 0.f), h0, l0);
                        bsplit(fmaxf(d[mt][nt][3], 0.f), h1, l1);
                        g_msgh[(size_t)(gm + 8) * MPAD + gn]     = h0;
                        g_msgh[(size_t)(gm + 8) * MPAD + gn + 1] = h1;
                        g_msgl[(size_t)(gm + 8) * MPAD + gn]     = l0;
                        g_msgl[(size_t)(gm + 8) * MPAD + gn + 1] = l1;
                    }
                }
            }
        }
    }
}

// =============== old-style GEMM, kept for MODE 2 ==============================
#define A_SZ (BM * ASTR)
#define SMEM_BYTES_OLD ((4 * A_SZ + 4 * B_SZ) * 2)

template<int KCH, int KSTR>
__launch_bounds__(256)
__global__ void mma_gemm_out_k(const float* __restrict__ bias,
                               const int*   __restrict__ molids,
                               float*       __restrict__ out)
{
    extern __shared__ __nv_bfloat16 sm[];
    __nv_bfloat16* Ah = sm;
    __nv_bfloat16* Al = sm + 2 * A_SZ;
    __nv_bfloat16* Bh = sm + 4 * A_SZ;
    __nv_bfloat16* Bl = sm + 4 * A_SZ + 2 * B_SZ;

    const int tid  = threadIdx.x;
    const int lane = tid & 31;
    const int wid  = tid >> 5;
    const int wm   = (wid >> 1) * 32;
    const int wn   = (wid & 1) * 32;
    const int g    = lane >> 2;
    const int tg   = lane & 3;
    const int m0   = blockIdx.y * BM;
    const int n0   = blockIdx.x * BN;

    const int arow = tid >> 2;
    const int acol = (tid & 3) * 8;

    float d[2][4][4];
    #pragma unroll
    for (int mt = 0; mt < 2; mt++)
        #pragma unroll
        for (int nt = 0; nt < 4; nt++)
            #pragma unroll
            for (int r = 0; r < 4; r++) d[mt][nt][r] = 0.f;

    auto issue = [&](int c, int st) {
        const int k0 = c * 32;
        #pragma unroll
        for (int i = 0; i < 2; i++) {
            const int r = arow + i * 64;
            const size_t go = (size_t)(m0 + r) * KSTR + k0 + acol;
            cp16(Ah + st * A_SZ + r * ASTR + acol, g_cath + go);
            cp16(Al + st * A_SZ + r * ASTR + acol, g_catl + go);
        }
        const size_t go = (size_t)(n0 + arow) * KSTR + k0 + acol;
        cp16(Bh + st * B_SZ + arow * ASTR + acol, g_Woh + go);
        cp16(Bl + st * B_SZ + arow * ASTR + acol, g_Wol + go);
        cp_commit();
    };

    issue(0, 0);

    for (int c = 0; c < KCH; c++) {
        const int st = c & 1;
        if (c + 1 < KCH) { issue(c + 1, (c + 1) & 1); cp_wait<1>(); }
        else             { cp_wait<0>(); }
        __syncthreads();

        const __nv_bfloat16* sAh = Ah + st * A_SZ;
        const __nv_bfloat16* sAl = Al + st * A_SZ;
        const __nv_bfloat16* sBh = Bh + st * B_SZ;
        const __nv_bfloat16* sBl = Bl + st * B_SZ;

        #pragma unroll
        for (int kk = 0; kk < 32; kk += 16) {
            uint32_t ah[2][4], al[2][4], bh[4][2], bl[4][2];
            #pragma unroll
            for (int mt = 0; mt < 2; mt++) {
                const int row = wm + mt * 16;
                ah[mt][0] = *(const uint32_t*)&sAh[(row + g    ) * ASTR + kk + 2*tg    ];
                ah[mt][1] = *(const uint32_t*)&sAh[(row + g + 8) * ASTR + kk + 2*tg    ];
                ah[mt][2] = *(const uint32_t*)&sAh[(row + g    ) * ASTR + kk + 2*tg + 8];
                ah[mt][3] = *(const uint32_t*)&sAh[(row + g + 8) * ASTR + kk + 2*tg + 8];
                al[mt][0] = *(const uint32_t*)&sAl[(row + g    ) * ASTR + kk + 2*tg    ];
                al[mt][1] = *(const uint32_t*)&sAl[(row + g + 8) * ASTR + kk + 2*tg    ];
                al[mt][2] = *(const uint32_t*)&sAl[(row + g    ) * ASTR + kk + 2*tg + 8];
                al[mt][3] = *(const uint32_t*)&sAl[(row + g + 8) * ASTR + kk + 2*tg + 8];
            }
            #pragma unroll
            for (int nt = 0; nt < 4; nt++) {
                const int col = wn + nt * 8 + g;
                bh[nt][0] = *(const uint32_t*)&sBh[col * ASTR + kk + 2*tg    ];
                bh[nt][1] = *(const uint32_t*)&sBh[col * ASTR + kk + 2*tg + 8];
                bl[nt][0] = *(const uint32_t*)&sBl[col * ASTR + kk + 2*tg    ];
                bl[nt][1] = *(const uint32_t*)&sBl[col * ASTR + kk + 2*tg + 8];
            }
            #pragma unroll
            for (int mt = 0; mt < 2; mt++)
                #pragma unroll
                for (int nt = 0; nt < 4; nt++) {
                    mma_bf16(d[mt][nt], ah[mt], bh[nt]);
                    mma_bf16(d[mt][nt], ah[mt], bl[nt]);
                    mma_bf16(d[mt][nt], al[mt], bh[nt]);
                }
        }
        __syncthreads();
    }

    #pragma unroll
    for (int mt = 0; mt < 2; mt++) {
        const int gm = m0 + wm + mt * 16 + g;
        const int mol0 = molids[gm];
        const int mol1 = molids[gm + 8];
        #pragma unroll
        for (int nt = 0; nt < 4; nt++) {
            const int gn = n0 + wn + nt * 8 + 2 * tg;
            if (gn < HIDDEN) {
                const float b0 = bias[gn], b1 = bias[gn + 1];
                atomicAdd(&out[mol0 * HIDDEN + gn],     fmaxf(d[mt][nt][0] + b0, 0.f));
                atomicAdd(&out[mol0 * HIDDEN + gn + 1], fmaxf(d[mt][nt][1] + b1, 0.f));
                atomicAdd(&out[mol1 * HIDDEN + gn],     fmaxf(d[mt][nt][2] + b0, 0.f));
                atomicAdd(&out[mol1 * HIDDEN + gn + 1], fmaxf(d[mt][nt][3] + b1, 0.f));
            }
        }
    }
}

// ---------------- prep kernels ------------------------------------------------
template<int K, int KP>
__global__ void split_W_k(const float* __restrict__ W)
{
    const int i = blockIdx.x * blockDim.x + threadIdx.x;
    if (i >= MPAD * KP) return;
    const int n = i / KP;
    const int k = i - n * KP;
    __nv_bfloat16 h = __float2bfloat16(0.f), l = h;
    if (n < HIDDEN && k < K) bsplit(W[k * HIDDEN + n], h, l);
    ((__nv_bfloat16*)((KP == MPAD) ? g_Wth : (KP == FEPAD) ? g_Wih : g_Woh))[i] = h;
    ((__nv_bfloat16*)((KP == MPAD) ? g_Wtl : (KP == FEPAD) ? g_Wil : g_Wol))[i] = l;
}

__global__ void split_fe_k(const float* __restrict__ fe)
{
    const int i = blockIdx.x * blockDim.x + threadIdx.x;
    if (i >= N_EDGES * FEPAD) return;
    const int m = i / FEPAD;
    const int k = i - m * FEPAD;
    __nv_bfloat16 h = __float2bfloat16(0.f), l = h;
    if (k < EDGE_FDIM) bsplit(fe[m * EDGE_FDIM + k], h, l);
    g_feh[i] = h;
    g_fel[i] = l;
}

__global__ void split_cat_k(const float* __restrict__ fn)
{
    const int i = blockIdx.x * blockDim.x + threadIdx.x;
    if (i >= N_NODES * CATPAD) return;
    const int m = i / CATPAD;
    const int k = i - m * CATPAD;
    __nv_bfloat16 h = __float2bfloat16(0.f), l = h;
    if (k < NODE_FDIM) bsplit(fn[m * NODE_FDIM + k], h, l);
    else if (k < NODE_FDIM + HIDDEN) bsplit(g_S[m * HIDDEN + (k - NODE_FDIM)], h, l);
    g_cath[i] = h;
    g_catl[i] = l;
}

__global__ void pad_msg_k()
{
    const int i = blockIdx.x * blockDim.x + threadIdx.x;
    if (i >= N_EDGES * (MPAD - HIDDEN)) return;
    const int e = i / (MPAD - HIDDEN);
    const int j = i - e * (MPAD - HIDDEN);
    const __nv_bfloat16 z = __float2bfloat16(0.f);
    g_msgh[(size_t)e * MPAD + HIDDEN + j] = z;
    g_msgl[(size_t)e * MPAD + HIDDEN + j] = z;
}

// ---------------- S[v] = sum_{k<6} X[n2e[v,k]] --------------------------------
template<int SRC>
__global__ void node_agg_k(const int* __restrict__ n2e)
{
    const int idx = blockIdx.x * blockDim.x + threadIdx.x;
    if (idx >= N_NODES * H4) return;
    const int v = idx / H4;
    const int c = idx - v * H4;
    float4 s = make_float4(0.f, 0.f, 0.f, 0.f);
    #pragma unroll
    for (int k = 0; k < MAX_NB; k++) {
        const int e = __ldg(&n2e[v * MAX_NB + k]);
        if (SRC == 0) {
            const float4 gg = __ldg(&((const float4*)g_G)[e * H4 + c]);
            s.x += gg.x; s.y += gg.y; s.z += gg.z; s.w += gg.w;
        } else {
            const size_t off = (size_t)e * MPAD + c * 4;
            const uint2 uh = *(const uint2*)&g_msgh[off];
            const uint2 ul = *(const uint2*)&g_msgl[off];
            const float2 h0 = __bfloat1622float2(*(const __nv_bfloat162*)&uh.x);
            const float2 h1 = __bfloat1622float2(*(const __nv_bfloat162*)&uh.y);
            const float2 l0 = __bfloat1622float2(*(const __nv_bfloat162*)&ul.x);
            const float2 l1 = __bfloat1622float2(*(const __nv_bfloat162*)&ul.y);
            s.x += h0.x + l0.x; s.y += h0.y + l0.y;
            s.z += h1.x + l1.x; s.w += h1.y + l1.y;
        }
    }
    ((float4*)g_S)[idx] = s;
}

// -------- msg[e] = relu(inp[e] + S[e2n[e]] - G[rev[e]]) -----------------------
__global__ void edge_update_k(const int* __restrict__ e2n,
                              const int* __restrict__ e2rev)
{
    const int idx = blockIdx.x * blockDim.x + threadIdx.x;
    if (idx >= N_EDGES * H4) return;
    const int e = idx / H4;
    const int c = idx - e * H4;
    const int v   = __ldg(&e2n[e]);
    const int rev = __ldg(&e2rev[e]);
    const float4 pi = ((const float4*)g_inp)[idx];
    const float4 ps = __ldg(&((const float4*)g_S)[v * H4 + c]);
    const float4 pg = __ldg(&((const float4*)g_G)[rev * H4 + c]);
    float m[4];
    m[0] = fmaxf(pi.x + ps.x - pg.x, 0.f);
    m[1] = fmaxf(pi.y + ps.y - pg.y, 0.f);
    m[2] = fmaxf(pi.z + ps.z - pg.z, 0.f);
    m[3] = fmaxf(pi.w + ps.w - pg.w, 0.f);
    __nv_bfloat16 h[4], l[4];
    #pragma unroll
    for (int j = 0; j < 4; j++) bsplit(m[j], h[j], l[j]);
    const size_t off = (size_t)e * MPAD + c * 4;
    *(uint2*)&g_msgh[off] = *(const uint2*)h;
    *(uint2*)&g_msgl[off] = *(const uint2*)l;
}

// ---------------- init / count / divide ---------------------------------------
__global__ void zero_out_k(float* __restrict__ out)
{
    const int i = blockIdx.x * blockDim.x + threadIdx.x;
    if (i < N_MOLS * HIDDEN) out[i] = 0.f;
    if (i < N_MOLS) g_cnt[i] = 0;
}

__global__ void count_k(const int* __restrict__ mol_ids)
{
    const int v = blockIdx.x * blockDim.x + threadIdx.x;
    if (v < N_NODES) atomicAdd(&g_cnt[mol_ids[v]], 1);
}

__global__ void divide_k(float* __restrict__ out)
{
    const int i = blockIdx.x * blockDim.x + threadIdx.x;
    if (i >= N_MOLS * HIDDEN) return;
    const int m = i / HIDDEN;
    const int c = g_cnt[m];
    out[i] = (c > 0) ? out[i] / (float)c : 0.f;
}

// ------------------------------------------------------------------------------
extern "C" void kernel_launch(void* const* d_in, const int* in_sizes, int n_in,
                              void* d_out, int out_size)
{
    const float* f_nodes = (const float*)d_in[0];
    const float* f_edges = (const float*)d_in[1];
    const float* W_i     = (const float*)d_in[2];
    const float* W_h     = (const float*)d_in[3];
    const float* W_o     = (const float*)d_in[4];
    const float* b_o     = (const float*)d_in[5];
    const int*   n2e     = (const int*)d_in[6];
    const int*   e2n     = (const int*)d_in[7];
    const int*   e2rev   = (const int*)d_in[8];
    const int*   mol_ids = (const int*)d_in[9];
    float* out = (float*)d_out;

    const int SM0 = (2 * 10 * A_CH + 4 * B_SZ) * 2;   // 225280
    const int SM1 = (2 * 5  * A_CH + 4 * B_SZ) * 2;   // 122880

    cudaFuncSetAttribute(mma_gemm_ares_k<0, 10, MPAD>,
                         cudaFuncAttributeMaxDynamicSharedMemorySize, SM0);
    cudaFuncSetAttribute(mma_gemm_ares_k<1, 5, FEPAD>,
                         cudaFuncAttributeMaxDynamicSharedMemorySize, SM1);
    cudaFuncSetAttribute(mma_gemm_out_k<14, CATPAD>,
                         cudaFuncAttributeMaxDynamicSharedMemorySize, SMEM_BYTES_OLD);

    zero_out_k<<<(N_MOLS * HIDDEN + 255) / 256, 256>>>(out);
    count_k<<<(N_NODES + 255) / 256, 256>>>(mol_ids);
    split_W_k<HIDDEN, MPAD>  <<<(MPAD * MPAD   + 255) / 256, 256>>>(W_h);
    split_W_k<EDGE_FDIM, FEPAD><<<(MPAD * FEPAD + 255) / 256, 256>>>(W_i);
    split_W_k<NODE_FDIM + HIDDEN, CATPAD><<<(MPAD * CATPAD + 255) / 256, 256>>>(W_o);
    split_fe_k<<<(N_EDGES * FEPAD + 255) / 256, 256>>>(f_edges);
    pad_msg_k<<<(N_EDGES * (MPAD - HIDDEN) + 255) / 256, 256>>>();

    // inp = f_edges @ W_i ; msg = relu(inp) split bf16  (A-resident GEMM)
    mma_gemm_ares_k<1, 5, FEPAD><<<N_EDGES / BM, 256, SM1>>>();

    const int aggBlocks  = (N_NODES * H4 + 255) / 256;
    const int edgeBlocks = (N_EDGES * H4 + 255) / 256;

    for (int it = 0; it < DEPTH - 1; it++) {
        // G = msg @ W_h  (A-resident GEMM: A loaded once, n-loop in kernel)
        mma_gemm_ares_k<0, 10, MPAD><<<N_EDGES / BM, 256, SM0>>>();
        // S[v] = sum_k G[n2e[v,k]]
        node_agg_k<0><<<aggBlocks, 256>>>(n2e);
        // msg[e] = relu(inp[e] + S[e2n[e]] - G[rev[e]]) -> bf16 hi/lo
        edge_update_k<<<edgeBlocks, 256>>>(e2n, e2rev);
    }

    // final neighbor sum of messages into S
    node_agg_k<1><<<aggBlocks, 256>>>(n2e);

    // concat split, then out GEMM (old-style, atomic seg-sum epilogue)
    split_cat_k<<<(N_NODES * CATPAD + 255) / 256, 256>>>(f_nodes);
    {
        const dim3 gridN(MPAD / BN, N_NODES / BM);
        mma_gemm_out_k<14, CATPAD><<<gridN, 256, SMEM_BYTES_OLD>>>(b_o, mol_ids, out);
    }

    // mean
    divide_k<<<(N_MOLS * HIDDEN + 255) / 256, 256>>>(out);
}